// round 2
// baseline (speedup 1.0000x reference)
#include <cuda_runtime.h>
#include <math.h>

#define C2 340
#define HID 170

// Scratch: z intermediate [4][340][256][256] fp32  (~356 MB, static device array)
__device__ float g_z[(size_t)4 * C2 * 256 * 256];
// Per-channel 8x8 spatial circular-conv kernel = irfft2(fft_filter)
__device__ float g_k[C2 * 64];

// ---------------------------------------------------------------------------
// Kernel P: k_c[dx][dy] = (1/64) * sum_{u,v in 0..7} G[u,v] cos(2*pi*(u*dx+v*dy)/8)
// G[u,v] = F[u,v] for v<=4, else F[(8-u)&7][8-v]  (Hermitian mirror; F real)
// ---------------------------------------------------------------------------
__global__ void prep_kernel(const float* __restrict__ F) {
    int c = blockIdx.x;
    int t = threadIdx.x;          // 64 threads: t = dx*8 + dy
    int dx = t >> 3, dy = t & 7;
    float s = 0.f;
#pragma unroll
    for (int u = 0; u < 8; u++) {
#pragma unroll
        for (int v = 0; v < 8; v++) {
            float g = (v <= 4) ? F[c * 40 + u * 5 + v]
                               : F[c * 40 + ((8 - u) & 7) * 5 + (8 - v)];
            int m = (u * dx + v * dy) & 7;
            s += g * cospif((float)m * 0.25f);
        }
    }
    g_k[c * 64 + t] = s * 0.015625f;   // 1/64
}

// ---------------------------------------------------------------------------
// Kernel A: per 8x8 patch:  t[o][.] = W_in[o,:] . x[:, .]   (64->340 channel mix)
//           z[o][n]        = sum_m t[o][m] * k_o[(n-m) mod (8,8)]
// Block = one patch (4096 blocks), 256 threads = 8 warps.
// Lane layout: lane = o_sub*8 + nx  (4 out-channels x 8 rows per warp).
// ---------------------------------------------------------------------------
__global__ __launch_bounds__(256) void kernelA(const float* __restrict__ x,
                                               const float* __restrict__ Win) {
    __shared__ float xs[4096];    // [c][pix]  pix = pr*8+pc
    __shared__ float Wsh[2048];   // 32 rows of W_in
    __shared__ float ksh[2048];   // 32 rows of k
    __shared__ float tsh[2048];   // 32 rows of t

    int pidx = blockIdx.x;                 // b*1024 + py*32 + px
    int b = pidx >> 10, py = (pidx >> 5) & 31, px = pidx & 31;
    int tid = threadIdx.x;

    const float* xb = x + (size_t)b * 64 * 65536 + (size_t)(py * 8) * 256 + px * 8;
    for (int i = tid; i < 1024; i += 256) {
        int c = i >> 4;
        int p4 = (i & 15) * 4;             // pixel quad
        int pr = p4 >> 3, pc = p4 & 7;
        float4 v = *(const float4*)(xb + (size_t)c * 65536 + pr * 256 + pc);
        *(float4*)(xs + c * 64 + p4) = v;
    }

    int wid = tid >> 5, lane = tid & 31;
    int o_sub = lane >> 3, nx = lane & 7;
    int o_local = wid * 4 + o_sub;

    for (int it = 0; it < 11; it++) {
        int obase = it * 32;
        int olim = min(32, C2 - obase);
        __syncthreads();
        {   // stage 32 contiguous rows of W_in and k
            const float4* wsrc = (const float4*)(Win + obase * 64);
            const float4* ksrc = (const float4*)(g_k + obase * 64);
            int n4 = olim * 16;
            for (int i = tid; i < n4; i += 256) {
                ((float4*)Wsh)[i] = wsrc[i];
                ((float4*)ksh)[i] = ksrc[i];
            }
        }
        __syncthreads();
        bool act = (o_local < olim);
        if (act) {
            // matmul phase: this lane computes t[o][row=nx][0..7]
            float tr[8] = {0, 0, 0, 0, 0, 0, 0, 0};
            const float4* w4 = (const float4*)(Wsh + o_local * 64);
#pragma unroll
            for (int c4 = 0; c4 < 16; c4++) {
                float4 w = w4[c4];
#pragma unroll
                for (int cc = 0; cc < 4; cc++) {
                    float wv = (cc == 0) ? w.x : (cc == 1) ? w.y : (cc == 2) ? w.z : w.w;
                    const float4* xr = (const float4*)(xs + (c4 * 4 + cc) * 64 + nx * 8);
                    float4 a = xr[0], bq = xr[1];
                    tr[0] = fmaf(wv, a.x, tr[0]);
                    tr[1] = fmaf(wv, a.y, tr[1]);
                    tr[2] = fmaf(wv, a.z, tr[2]);
                    tr[3] = fmaf(wv, a.w, tr[3]);
                    tr[4] = fmaf(wv, bq.x, tr[4]);
                    tr[5] = fmaf(wv, bq.y, tr[5]);
                    tr[6] = fmaf(wv, bq.z, tr[6]);
                    tr[7] = fmaf(wv, bq.w, tr[7]);
                }
            }
            float4* tp = (float4*)(tsh + o_local * 64 + nx * 8);
            tp[0] = make_float4(tr[0], tr[1], tr[2], tr[3]);
            tp[1] = make_float4(tr[4], tr[5], tr[6], tr[7]);
        }
        __syncwarp();
        if (act) {
            // circular-conv phase: compile-time wrap indices, all-register FFMA
            float acc[8] = {0, 0, 0, 0, 0, 0, 0, 0};
#pragma unroll
            for (int mx = 0; mx < 8; mx++) {
                const float4* tp = (const float4*)(tsh + o_local * 64 + mx * 8);
                float4 ta = tp[0], tb = tp[1];
                float tv[8] = {ta.x, ta.y, ta.z, ta.w, tb.x, tb.y, tb.z, tb.w};
                int dxr = (nx - mx) & 7;
                const float4* kp = (const float4*)(ksh + o_local * 64 + dxr * 8);
                float4 ka = kp[0], kb = kp[1];
                float kv[8] = {ka.x, ka.y, ka.z, ka.w, kb.x, kb.y, kb.z, kb.w};
#pragma unroll
                for (int my = 0; my < 8; my++) {
#pragma unroll
                    for (int ny = 0; ny < 8; ny++) {
                        acc[ny] = fmaf(tv[my], kv[(ny - my) & 7], acc[ny]);
                    }
                }
            }
            int o = obase + o_local;
            float* zp = g_z + (((size_t)b * C2 + o) * 256 + py * 8 + nx) * 256 + px * 8;
            *(float4*)zp       = make_float4(acc[0], acc[1], acc[2], acc[3]);
            *(float4*)(zp + 4) = make_float4(acc[4], acc[5], acc[6], acc[7]);
        }
    }
}

// ---------------------------------------------------------------------------
// Kernel B: fused depthwise 3x3 (zero pad) + exact GELU gate + project_out.
// Block = 32x8 pixel tile, 256 threads, double-buffered halo tiles per channel.
// out[o,p] = sum_h W_out[o,h] * gelu(dw(z[h],p)) * dw(z[h+170],p)
// ---------------------------------------------------------------------------
__global__ __launch_bounds__(256) void kernelB(const float* __restrict__ Wdw,
                                               const float* __restrict__ Wout,
                                               float* __restrict__ out) {
    __shared__ float Wt[HID * 64];        // Wt[h][o] = Wout[o][h]  (broadcast reads)
    __shared__ float sb[2][2][340];       // [buf][half][10*34]

    int b = blockIdx.z;
    int r0 = blockIdx.y * 8, c0 = blockIdx.x * 32;
    int tid = threadIdx.x;

    for (int i = tid; i < HID * 64; i += 256) {
        int h = i >> 6, o = i & 63;
        Wt[i] = Wout[o * HID + h];
    }

    int tx = tid & 31, ty = tid >> 5;

    // halo-load assignment (10x34 = 340 elems, <=2 per thread), hoisted
    int i0 = tid;
    int rr0 = i0 / 34, cc0 = i0 % 34;
    int gr0 = r0 + rr0 - 1, gc0 = c0 + cc0 - 1;
    bool ok0 = (gr0 >= 0) && (gr0 < 256) && (gc0 >= 0) && (gc0 < 256);
    size_t off0 = (size_t)gr0 * 256 + gc0;
    int i1 = tid + 256;
    bool has1 = (i1 < 340);
    int rr1 = i1 / 34, cc1 = i1 % 34;
    int gr1 = r0 + rr1 - 1, gc1 = c0 + cc1 - 1;
    bool ok1 = has1 && (gr1 >= 0) && (gr1 < 256) && (gc1 >= 0) && (gc1 < 256);
    size_t off1 = (size_t)gr1 * 256 + gc1;

    const float* zb = g_z + (size_t)b * C2 * 65536;

    float acc[64];
#pragma unroll
    for (int o = 0; o < 64; o++) acc[o] = 0.f;

    {   // preload h = 0
        const float* z1 = zb;
        const float* z2 = zb + (size_t)HID * 65536;
        float v10 = ok0 ? z1[off0] : 0.f;
        float v20 = ok0 ? z2[off0] : 0.f;
        float v11 = ok1 ? z1[off1] : 0.f;
        float v21 = ok1 ? z2[off1] : 0.f;
        sb[0][0][i0] = v10; sb[0][1][i0] = v20;
        if (has1) { sb[0][0][i1] = v11; sb[0][1][i1] = v21; }
    }
    __syncthreads();

    for (int h = 0; h < HID; h++) {
        // issue next-channel loads early (latency overlapped with compute)
        float v10 = 0.f, v20 = 0.f, v11 = 0.f, v21 = 0.f;
        if (h + 1 < HID) {
            const float* z1 = zb + (size_t)(h + 1) * 65536;
            const float* z2 = z1 + (size_t)HID * 65536;
            v10 = ok0 ? z1[off0] : 0.f;
            v20 = ok0 ? z2[off0] : 0.f;
            v11 = ok1 ? z1[off1] : 0.f;
            v21 = ok1 ? z2[off1] : 0.f;
        }

        const float* s1 = sb[h & 1][0];
        const float* s2 = sb[h & 1][1];
        float w1[9], w2[9];
#pragma unroll
        for (int j = 0; j < 9; j++) {
            w1[j] = __ldg(Wdw + h * 9 + j);
            w2[j] = __ldg(Wdw + (h + HID) * 9 + j);
        }
        float d1 = 0.f, d2 = 0.f;
#pragma unroll
        for (int i = 0; i < 3; i++) {
#pragma unroll
            for (int j = 0; j < 3; j++) {
                d1 = fmaf(s1[(ty + i) * 34 + tx + j], w1[i * 3 + j], d1);
                d2 = fmaf(s2[(ty + i) * 34 + tx + j], w2[i * 3 + j], d2);
            }
        }
        // exact GELU: 0.5*x*(1+erf(x/sqrt(2))), gated by d2
        float g = 0.5f * d1 * (1.f + erff(d1 * 0.7071067811865476f)) * d2;

        const float* wth = Wt + h * 64;
#pragma unroll
        for (int o = 0; o < 64; o++) acc[o] = fmaf(g, wth[o], acc[o]);

        // stage next buffer, then one barrier
        int nb = (h + 1) & 1;
        sb[nb][0][i0] = v10; sb[nb][1][i0] = v20;
        if (has1) { sb[nb][0][i1] = v11; sb[nb][1][i1] = v21; }
        __syncthreads();
    }

    int r = r0 + ty, c = c0 + tx;
    float* op = out + ((size_t)b * 64 * 256 + r) * 256 + c;
#pragma unroll
    for (int o = 0; o < 64; o++) op[(size_t)o * 65536] = acc[o];
}

// ---------------------------------------------------------------------------
extern "C" void kernel_launch(void* const* d_in, const int* in_sizes, int n_in,
                              void* d_out, int out_size) {
    const float* x    = (const float*)d_in[0];  // [4,64,256,256]
    const float* Win  = (const float*)d_in[1];  // [340,64]
    const float* Wdw  = (const float*)d_in[2];  // [340,1,3,3]
    const float* Ff   = (const float*)d_in[3];  // [340,1,1,8,5]
    const float* Wout = (const float*)d_in[4];  // [64,170]
    float* out = (float*)d_out;                 // [4,64,256,256]

    prep_kernel<<<C2, 64>>>(Ff);
    kernelA<<<4096, 256>>>(x, Win);
    dim3 gb(8, 32, 4);
    kernelB<<<gb, 256>>>(Wdw, Wout, out);
}

// round 4
// speedup vs baseline: 1.6346x; 1.6346x over previous
#include <cuda_runtime.h>
#include <math.h>

#define C2 340
#define HID 170

// Scratch: z intermediate [4][340][256][256] fp32  (~356 MB, static device array)
__device__ float g_z[(size_t)4 * C2 * 256 * 256];
// Per-channel 8x8 spatial circular-conv kernel = irfft2(fft_filter)
__device__ float g_k[C2 * 64];
// Transposed project_in weights: g_wt[c][o]  (c=0..63, o=0..339)
__device__ float g_wt[64 * C2];

// ---------------------------------------------------------------------------
// Kernel P: k_c[dx][dy] = (1/64) * sum_{u,v} G[u,v] cos(2*pi*(u*dx+v*dy)/8)
// G[u,v] = F[u,v] for v<=4, else F[(8-u)&7][8-v]  (Hermitian mirror; F real)
// Also transposes W_in into g_wt for coalesced 4-wide reads in kernelA.
// ---------------------------------------------------------------------------
__global__ void prep_kernel(const float* __restrict__ F,
                            const float* __restrict__ Win) {
    int c = blockIdx.x;           // output channel o (0..339)
    int t = threadIdx.x;          // 64 threads: t = dx*8 + dy
    int dx = t >> 3, dy = t & 7;
    float s = 0.f;
#pragma unroll
    for (int u = 0; u < 8; u++) {
#pragma unroll
        for (int v = 0; v < 8; v++) {
            float g = (v <= 4) ? F[c * 40 + u * 5 + v]
                               : F[c * 40 + ((8 - u) & 7) * 5 + (8 - v)];
            int m = (u * dx + v * dy) & 7;
            s += g * cospif((float)m * 0.25f);
        }
    }
    g_k[c * 64 + t] = s * 0.015625f;   // 1/64
    // transpose W_in: g_wt[cin][o] = W_in[o][cin]
    g_wt[t * C2 + c] = Win[c * 64 + t];
}

// ---------------------------------------------------------------------------
// Kernel A: per 8x8 patch:  t[o][.] = W_in[o,:] . x[:, .]   (64->340 mix)
//           z[o][n]        = sum_m t[o][m] * k_o[(n-m) mod (8,8)]
// Block = one patch (4096 blocks), 256 threads.
// Thread layout: nx = tid&7 (pixel row), og = tid>>3; each thread owns a
// 4-o x 8-pixel register tile in both phases. o processed in chunks of 128.
// ---------------------------------------------------------------------------
__global__ __launch_bounds__(256, 2) void kernelA(const float* __restrict__ x) {
    __shared__ float xs[4096];        // [c][pix]   16 KB
    __shared__ float tsh[128 * 64];   // [o_local][pix]  32 KB

    int pidx = blockIdx.x;                 // b*1024 + py*32 + px
    int b = pidx >> 10, py = (pidx >> 5) & 31, px = pidx & 31;
    int tid = threadIdx.x;

    const float* xb = x + (size_t)b * 64 * 65536 + (size_t)(py * 8) * 256 + px * 8;
    for (int i = tid; i < 1024; i += 256) {
        int c = i >> 4;
        int p4 = (i & 15) * 4;
        int pr = p4 >> 3, pc = p4 & 7;
        *(float4*)(xs + c * 64 + p4) =
            *(const float4*)(xb + (size_t)c * 65536 + pr * 256 + pc);
    }

    int og = tid >> 3, nx = tid & 7;
    int o_local = og * 4;
    float* zbase = g_z + ((size_t)b * C2) * 65536 + (size_t)(py * 8 + nx) * 256 + px * 8;

#pragma unroll 1
    for (int chunk = 0; chunk < 3; chunk++) {
        int obase = chunk << 7;
        int ocnt = min(128, C2 - obase);
        bool act = (o_local < ocnt);
        __syncthreads();              // xs ready (iter 0) / tsh reads done (iter>0)

        float t[4][8];
        if (act) {
#pragma unroll
            for (int j = 0; j < 4; j++)
#pragma unroll
                for (int p = 0; p < 8; p++) t[j][p] = 0.f;

            const float* wp = g_wt + obase + o_local;
            const float* xr = xs + nx * 8;
#pragma unroll 4
            for (int c = 0; c < 64; c++) {
                float4 w = *(const float4*)(wp + c * C2);
                float4 a = *(const float4*)(xr + c * 64);
                float4 bq = *(const float4*)(xr + c * 64 + 4);
                float wv[4] = {w.x, w.y, w.z, w.w};
                float xv[8] = {a.x, a.y, a.z, a.w, bq.x, bq.y, bq.z, bq.w};
#pragma unroll
                for (int j = 0; j < 4; j++)
#pragma unroll
                    for (int p = 0; p < 8; p++)
                        t[j][p] = fmaf(wv[j], xv[p], t[j][p]);
            }
            // stage t rows for the conv phase
#pragma unroll
            for (int j = 0; j < 4; j++) {
                float* tp = tsh + (o_local + j) * 64 + nx * 8;
                *(float4*)tp       = make_float4(t[j][0], t[j][1], t[j][2], t[j][3]);
                *(float4*)(tp + 4) = make_float4(t[j][4], t[j][5], t[j][6], t[j][7]);
            }
        }
        __syncthreads();

        if (act) {
            float acc[4][8];
#pragma unroll
            for (int j = 0; j < 4; j++)
#pragma unroll
                for (int p = 0; p < 8; p++) acc[j][p] = 0.f;

#pragma unroll 1
            for (int mx = 0; mx < 8; mx++) {
                int dxr = (nx - mx) & 7;
#pragma unroll
                for (int j = 0; j < 4; j++) {
                    const float4* tp = (const float4*)(tsh + (o_local + j) * 64 + mx * 8);
                    float4 ta = tp[0], tb = tp[1];
                    float tv[8] = {ta.x, ta.y, ta.z, ta.w, tb.x, tb.y, tb.z, tb.w};
                    const float4* kp =
                        (const float4*)(g_k + (obase + o_local + j) * 64 + dxr * 8);
                    float4 ka = kp[0], kb = kp[1];
                    float kv[8] = {ka.x, ka.y, ka.z, ka.w, kb.x, kb.y, kb.z, kb.w};
#pragma unroll
                    for (int my = 0; my < 8; my++)
#pragma unroll
                        for (int ny = 0; ny < 8; ny++)
                            acc[j][ny] = fmaf(tv[my], kv[(ny - my) & 7], acc[j][ny]);
                }
            }
#pragma unroll
            for (int j = 0; j < 4; j++) {
                float* zp = zbase + (size_t)(obase + o_local + j) * 65536;
                *(float4*)zp       = make_float4(acc[j][0], acc[j][1], acc[j][2], acc[j][3]);
                *(float4*)(zp + 4) = make_float4(acc[j][4], acc[j][5], acc[j][6], acc[j][7]);
            }
        }
    }
}

// ---------------------------------------------------------------------------
// Kernel B: fused depthwise 3x3 (zero pad) + exact GELU gate + project_out.
// Block = 32x8 pixel tile, 256 threads, double-buffered halo tiles per channel.
// out[o,p] = sum_h W_out[o,h] * gelu(dw(z[h],p)) * dw(z[h+170],p)
// ---------------------------------------------------------------------------
__global__ __launch_bounds__(256) void kernelB(const float* __restrict__ Wdw,
                                               const float* __restrict__ Wout,
                                               float* __restrict__ out) {
    __shared__ float Wt[HID * 64];        // Wt[h][o] = Wout[o][h]  (broadcast reads)
    __shared__ float sb[2][2][340];       // [buf][half][10*34]

    int b = blockIdx.z;
    int r0 = blockIdx.y * 8, c0 = blockIdx.x * 32;
    int tid = threadIdx.x;

    for (int i = tid; i < HID * 64; i += 256) {
        int h = i >> 6, o = i & 63;
        Wt[i] = Wout[o * HID + h];
    }

    int tx = tid & 31, ty = tid >> 5;

    int i0 = tid;
    int rr0 = i0 / 34, cc0 = i0 % 34;
    int gr0 = r0 + rr0 - 1, gc0 = c0 + cc0 - 1;
    bool ok0 = (gr0 >= 0) && (gr0 < 256) && (gc0 >= 0) && (gc0 < 256);
    size_t off0 = (size_t)gr0 * 256 + gc0;
    int i1 = tid + 256;
    bool has1 = (i1 < 340);
    int rr1 = i1 / 34, cc1 = i1 % 34;
    int gr1 = r0 + rr1 - 1, gc1 = c0 + cc1 - 1;
    bool ok1 = has1 && (gr1 >= 0) && (gr1 < 256) && (gc1 >= 0) && (gc1 < 256);
    size_t off1 = (size_t)gr1 * 256 + gc1;

    const float* zb = g_z + (size_t)b * C2 * 65536;

    float acc[64];
#pragma unroll
    for (int o = 0; o < 64; o++) acc[o] = 0.f;

    {   // preload h = 0
        const float* z1 = zb;
        const float* z2 = zb + (size_t)HID * 65536;
        float v10 = ok0 ? z1[off0] : 0.f;
        float v20 = ok0 ? z2[off0] : 0.f;
        float v11 = ok1 ? z1[off1] : 0.f;
        float v21 = ok1 ? z2[off1] : 0.f;
        sb[0][0][i0] = v10; sb[0][1][i0] = v20;
        if (has1) { sb[0][0][i1] = v11; sb[0][1][i1] = v21; }
    }
    __syncthreads();

    for (int h = 0; h < HID; h++) {
        float v10 = 0.f, v20 = 0.f, v11 = 0.f, v21 = 0.f;
        if (h + 1 < HID) {
            const float* z1 = zb + (size_t)(h + 1) * 65536;
            const float* z2 = z1 + (size_t)HID * 65536;
            v10 = ok0 ? z1[off0] : 0.f;
            v20 = ok0 ? z2[off0] : 0.f;
            v11 = ok1 ? z1[off1] : 0.f;
            v21 = ok1 ? z2[off1] : 0.f;
        }

        const float* s1 = sb[h & 1][0];
        const float* s2 = sb[h & 1][1];
        float w1[9], w2[9];
#pragma unroll
        for (int j = 0; j < 9; j++) {
            w1[j] = __ldg(Wdw + h * 9 + j);
            w2[j] = __ldg(Wdw + (h + HID) * 9 + j);
        }
        float d1 = 0.f, d2 = 0.f;
#pragma unroll
        for (int i = 0; i < 3; i++) {
#pragma unroll
            for (int j = 0; j < 3; j++) {
                d1 = fmaf(s1[(ty + i) * 34 + tx + j], w1[i * 3 + j], d1);
                d2 = fmaf(s2[(ty + i) * 34 + tx + j], w2[i * 3 + j], d2);
            }
        }
        float g = 0.5f * d1 * (1.f + erff(d1 * 0.7071067811865476f)) * d2;

        const float* wth = Wt + h * 64;
#pragma unroll
        for (int o = 0; o < 64; o++) acc[o] = fmaf(g, wth[o], acc[o]);

        int nb = (h + 1) & 1;
        sb[nb][0][i0] = v10; sb[nb][1][i0] = v20;
        if (has1) { sb[nb][0][i1] = v11; sb[nb][1][i1] = v21; }
        __syncthreads();
    }

    int r = r0 + ty, c = c0 + tx;
    float* op = out + ((size_t)b * 64 * 256 + r) * 256 + c;
#pragma unroll
    for (int o = 0; o < 64; o++) op[(size_t)o * 65536] = acc[o];
}

// ---------------------------------------------------------------------------
extern "C" void kernel_launch(void* const* d_in, const int* in_sizes, int n_in,
                              void* d_out, int out_size) {
    const float* x    = (const float*)d_in[0];  // [4,64,256,256]
    const float* Win  = (const float*)d_in[1];  // [340,64]
    const float* Wdw  = (const float*)d_in[2];  // [340,1,3,3]
    const float* Ff   = (const float*)d_in[3];  // [340,1,1,8,5]
    const float* Wout = (const float*)d_in[4];  // [64,170]
    float* out = (float*)d_out;                 // [4,64,256,256]

    prep_kernel<<<C2, 64>>>(Ff, Win);
    kernelA<<<4096, 256>>>(x);
    dim3 gb(8, 32, 4);
    kernelB<<<gb, 256>>>(Wdw, Wout, out);
}

// round 6
// speedup vs baseline: 1.6832x; 1.0297x over previous
#include <cuda_runtime.h>
#include <math.h>

#define C2 340
#define HID 170

typedef unsigned long long u64;

// Packed fp32x2 FMA (SASS FFMA2) — 2 IEEE-rn fp32 FMAs in one instruction.
__device__ __forceinline__ u64 ffma2(u64 a, u64 b, u64 c) {
    u64 d;
    asm("fma.rn.f32x2 %0, %1, %2, %3;" : "=l"(d) : "l"(a), "l"(b), "l"(c));
    return d;
}
__device__ __forceinline__ u64 pack2(float lo, float hi) {
    u64 d;
    asm("mov.b64 %0, {%1, %2};" : "=l"(d) : "f"(lo), "f"(hi));
    return d;
}
__device__ __forceinline__ void unpack2(u64 d, float& lo, float& hi) {
    asm("mov.b64 {%0, %1}, %2;" : "=f"(lo), "=f"(hi) : "l"(d));
}

// Scratch: z intermediate [4][340][256][256] fp32  (~356 MB)
__device__ float g_z[(size_t)4 * C2 * 256 * 256];
// Per-channel 8x8 spatial circular-conv kernel = irfft2(fft_filter)
__device__ float g_k[C2 * 64];
// Transposed project_in weights: g_wt[c][o]
__device__ float g_wt[64 * C2];

// ---------------------------------------------------------------------------
// Kernel P: k_c[dx][dy] = (1/64) * sum_{u,v} G[u,v] cos(2*pi*(u*dx+v*dy)/8)
// G[u,v] = F[u,v] for v<=4, else F[(8-u)&7][8-v]  (Hermitian mirror; F real)
// ---------------------------------------------------------------------------
__global__ void prep_kernel(const float* __restrict__ F,
                            const float* __restrict__ Win) {
    int c = blockIdx.x;
    int t = threadIdx.x;          // 64 threads: t = dx*8 + dy
    int dx = t >> 3, dy = t & 7;
    float s = 0.f;
#pragma unroll
    for (int u = 0; u < 8; u++) {
#pragma unroll
        for (int v = 0; v < 8; v++) {
            float g = (v <= 4) ? F[c * 40 + u * 5 + v]
                               : F[c * 40 + ((8 - u) & 7) * 5 + (8 - v)];
            int m = (u * dx + v * dy) & 7;
            s += g * cospif((float)m * 0.25f);
        }
    }
    g_k[c * 64 + t] = s * 0.015625f;
    g_wt[t * C2 + c] = Win[c * 64 + t];
}

// ---------------------------------------------------------------------------
// Kernel A: per 8x8 patch, project_in (64->340) + 64-tap circular conv.
// Thread layout: nx = tid&7 (pixel row), og = tid>>3; 4-o x 8-pixel register
// tile, computed as 4-o x 4 pixel-PAIRS with FFMA2.
// ---------------------------------------------------------------------------
__global__ __launch_bounds__(256, 2) void kernelA(const float* __restrict__ x) {
    __shared__ float xs[4096];        // [c][pix]   16 KB
    __shared__ float tsh[128 * 64];   // [o_local][pix]  32 KB

    int pidx = blockIdx.x;                 // b*1024 + py*32 + px
    int b = pidx >> 10, py = (pidx >> 5) & 31, px = pidx & 31;
    int tid = threadIdx.x;

    const float* xb = x + (size_t)b * 64 * 65536 + (size_t)(py * 8) * 256 + px * 8;
    for (int i = tid; i < 1024; i += 256) {
        int c = i >> 4;
        int p4 = (i & 15) * 4;
        int pr = p4 >> 3, pc = p4 & 7;
        *(float4*)(xs + c * 64 + p4) =
            *(const float4*)(xb + (size_t)c * 65536 + pr * 256 + pc);
    }

    int og = tid >> 3, nx = tid & 7;
    int o_local = og * 4;
    float* zbase = g_z + ((size_t)b * C2) * 65536 + (size_t)(py * 8 + nx) * 256 + px * 8;

#pragma unroll 1
    for (int chunk = 0; chunk < 3; chunk++) {
        int obase = chunk << 7;
        int ocnt = min(128, C2 - obase);
        bool act = (o_local < ocnt);
        __syncthreads();              // xs ready (iter 0) / tsh reads done (iter>0)

        u64 t2[4][4];
        if (act) {
#pragma unroll
            for (int j = 0; j < 4; j++)
#pragma unroll
                for (int q = 0; q < 4; q++) t2[j][q] = 0ull;

            const float* wp = g_wt + obase + o_local;
            const float* xr = xs + nx * 8;
#pragma unroll 4
            for (int c = 0; c < 64; c++) {
                float4 w = *(const float4*)(wp + c * C2);
                ulonglong2 xa = *(const ulonglong2*)(xr + c * 64);
                ulonglong2 xbq = *(const ulonglong2*)(xr + c * 64 + 4);
                u64 xv2[4] = {xa.x, xa.y, xbq.x, xbq.y};
                float wv[4] = {w.x, w.y, w.z, w.w};
#pragma unroll
                for (int j = 0; j < 4; j++) {
                    u64 w2 = pack2(wv[j], wv[j]);
#pragma unroll
                    for (int q = 0; q < 4; q++)
                        t2[j][q] = ffma2(w2, xv2[q], t2[j][q]);
                }
            }
#pragma unroll
            for (int j = 0; j < 4; j++) {
                float* tp = tsh + (o_local + j) * 64 + nx * 8;
                *(ulonglong2*)tp = make_ulonglong2(t2[j][0], t2[j][1]);
                *(ulonglong2*)(tp + 4) = make_ulonglong2(t2[j][2], t2[j][3]);
            }
        }
        __syncthreads();

        if (act) {
            u64 acc2[4][4];
#pragma unroll
            for (int j = 0; j < 4; j++)
#pragma unroll
                for (int q = 0; q < 4; q++) acc2[j][q] = 0ull;

#pragma unroll 1
            for (int mx = 0; mx < 8; mx++) {
                int dxr = (nx - mx) & 7;
#pragma unroll
                for (int j = 0; j < 4; j++) {
                    const float4* tp = (const float4*)(tsh + (o_local + j) * 64 + mx * 8);
                    float4 ta = tp[0], tb = tp[1];
                    float tv[8] = {ta.x, ta.y, ta.z, ta.w, tb.x, tb.y, tb.z, tb.w};
                    const float4* kp =
                        (const float4*)(g_k + (obase + o_local + j) * 64 + dxr * 8);
                    float4 ka = kp[0], kb = kp[1];
                    // aligned kv pairs (even my) and shifted pairs (odd my)
                    u64 kae[4] = {pack2(ka.x, ka.y), pack2(ka.z, ka.w),
                                  pack2(kb.x, kb.y), pack2(kb.z, kb.w)};
                    u64 kao[4] = {pack2(ka.y, ka.z), pack2(ka.w, kb.x),
                                  pack2(kb.y, kb.z), pack2(kb.w, ka.x)};
#pragma unroll
                    for (int my = 0; my < 8; my++) {
                        u64 tb2 = pack2(tv[my], tv[my]);
                        if ((my & 1) == 0) {
                            int s = my >> 1;
#pragma unroll
                            for (int q = 0; q < 4; q++)
                                acc2[j][q] = ffma2(tb2, kae[(q - s) & 3], acc2[j][q]);
                        } else {
                            int s = my >> 1;
#pragma unroll
                            for (int q = 0; q < 4; q++)
                                acc2[j][q] = ffma2(tb2, kao[(q - s - 1) & 3], acc2[j][q]);
                        }
                    }
                }
            }
#pragma unroll
            for (int j = 0; j < 4; j++) {
                float* zp = zbase + (size_t)(obase + o_local + j) * 65536;
                *(ulonglong2*)zp = make_ulonglong2(acc2[j][0], acc2[j][1]);
                *(ulonglong2*)(zp + 4) = make_ulonglong2(acc2[j][2], acc2[j][3]);
            }
        }
    }
}

// ---------------------------------------------------------------------------
// Kernel B: fused depthwise 3x3 (zero pad) + exact GELU gate + project_out.
// acc loop packed: 32 FFMA2 against u64 pairs of Wt row.
// ---------------------------------------------------------------------------
__global__ __launch_bounds__(256) void kernelB(const float* __restrict__ Wdw,
                                               const float* __restrict__ Wout,
                                               float* __restrict__ out) {
    __shared__ float Wt[HID * 64];        // Wt[h][o] = Wout[o][h]
    __shared__ float sb[2][2][340];       // [buf][half][10*34]

    int b = blockIdx.z;
    int r0 = blockIdx.y * 8, c0 = blockIdx.x * 32;
    int tid = threadIdx.x;

    for (int i = tid; i < HID * 64; i += 256) {
        int h = i >> 6, o = i & 63;
        Wt[i] = Wout[o * HID + h];
    }

    int tx = tid & 31, ty = tid >> 5;

    int i0 = tid;
    int rr0 = i0 / 34, cc0 = i0 % 34;
    int gr0 = r0 + rr0 - 1, gc0 = c0 + cc0 - 1;
    bool ok0 = (gr0 >= 0) && (gr0 < 256) && (gc0 >= 0) && (gc0 < 256);
    size_t off0 = (size_t)gr0 * 256 + gc0;
    int i1 = tid + 256;
    bool has1 = (i1 < 340);
    int rr1 = i1 / 34, cc1 = i1 % 34;
    int gr1 = r0 + rr1 - 1, gc1 = c0 + cc1 - 1;
    bool ok1 = has1 && (gr1 >= 0) && (gr1 < 256) && (gc1 >= 0) && (gc1 < 256);
    size_t off1 = (size_t)gr1 * 256 + gc1;

    const float* zb = g_z + (size_t)b * C2 * 65536;

    u64 acc2[32];
#pragma unroll
    for (int q = 0; q < 32; q++) acc2[q] = 0ull;

    {   // preload h = 0
        const float* z1 = zb;
        const float* z2 = zb + (size_t)HID * 65536;
        float v10 = ok0 ? z1[off0] : 0.f;
        float v20 = ok0 ? z2[off0] : 0.f;
        float v11 = ok1 ? z1[off1] : 0.f;
        float v21 = ok1 ? z2[off1] : 0.f;
        sb[0][0][i0] = v10; sb[0][1][i0] = v20;
        if (has1) { sb[0][0][i1] = v11; sb[0][1][i1] = v21; }
    }
    __syncthreads();

    for (int h = 0; h < HID; h++) {
        float v10 = 0.f, v20 = 0.f, v11 = 0.f, v21 = 0.f;
        if (h + 1 < HID) {
            const float* z1 = zb + (size_t)(h + 1) * 65536;
            const float* z2 = z1 + (size_t)HID * 65536;
            v10 = ok0 ? z1[off0] : 0.f;
            v20 = ok0 ? z2[off0] : 0.f;
            v11 = ok1 ? z1[off1] : 0.f;
            v21 = ok1 ? z2[off1] : 0.f;
        }

        const float* s1 = sb[h & 1][0];
        const float* s2 = sb[h & 1][1];
        float w1[9], w2[9];
#pragma unroll
        for (int j = 0; j < 9; j++) {
            w1[j] = __ldg(Wdw + h * 9 + j);
            w2[j] = __ldg(Wdw + (h + HID) * 9 + j);
        }
        float d1 = 0.f, d2 = 0.f;
#pragma unroll
        for (int i = 0; i < 3; i++) {
#pragma unroll
            for (int j = 0; j < 3; j++) {
                d1 = fmaf(s1[(ty + i) * 34 + tx + j], w1[i * 3 + j], d1);
                d2 = fmaf(s2[(ty + i) * 34 + tx + j], w2[i * 3 + j], d2);
            }
        }
        float g = 0.5f * d1 * (1.f + erff(d1 * 0.7071067811865476f)) * d2;
        u64 g2 = pack2(g, g);

        const u64* wt2 = (const u64*)(Wt + h * 64);
#pragma unroll
        for (int q = 0; q < 32; q++) acc2[q] = ffma2(g2, wt2[q], acc2[q]);

        int nb = (h + 1) & 1;
        sb[nb][0][i0] = v10; sb[nb][1][i0] = v20;
        if (has1) { sb[nb][0][i1] = v11; sb[nb][1][i1] = v21; }
        __syncthreads();
    }

    int r = r0 + ty, c = c0 + tx;
    float* op = out + ((size_t)b * 64 * 256 + r) * 256 + c;
#pragma unroll
    for (int q = 0; q < 32; q++) {
        float lo, hi;
        unpack2(acc2[q], lo, hi);
        op[(size_t)(2 * q) * 65536] = lo;
        op[(size_t)(2 * q + 1) * 65536] = hi;
    }
}

// ---------------------------------------------------------------------------
extern "C" void kernel_launch(void* const* d_in, const int* in_sizes, int n_in,
                              void* d_out, int out_size) {
    const float* x    = (const float*)d_in[0];  // [4,64,256,256]
    const float* Win  = (const float*)d_in[1];  // [340,64]
    const float* Wdw  = (const float*)d_in[2];  // [340,1,3,3]
    const float* Ff   = (const float*)d_in[3];  // [340,1,1,8,5]
    const float* Wout = (const float*)d_in[4];  // [64,170]
    float* out = (float*)d_out;                 // [4,64,256,256]

    prep_kernel<<<C2, 64>>>(Ff, Win);
    kernelA<<<4096, 256>>>(x);
    dim3 gb(8, 32, 4);
    kernelB<<<gb, 256>>>(Wdw, Wout, out);
}